// round 16
// baseline (speedup 1.0000x reference)
#include <cuda_runtime.h>
#include <cuda_fp16.h>
#include <math.h>

#define NEGV (-1e30f)

constexpr int C        = 256;
constexpr int LMAX     = 128;
constexpr int THREADS  = 512;   // 16 warps
constexpr int MAXB     = 64;
constexpr int P16PITCH = 272;   // halves per fp16 p copy (conflict-free reads/writes)
constexpr int GRID_PAD = 148;

__device__ float g_f  [MAXB][C];
__device__ float g_g  [MAXB][C];
__device__ float g_a  [MAXB][LMAX];
__device__ float g_bt [MAXB][LMAX];
__device__ float g_lsf[MAXB];
__device__ float g_lsg[MAXB];
__device__ int   g_bar = 0;

struct SmemLayout {
  __half p16A[2][4 * P16PITCH];   // fwd chain p
  __half p16B[2][4 * P16PITCH];   // bwd chain p
  float  xtA[2][C];
  float  xtB[2][C];
  float  nbA[2][LMAX + 2];
  float  nbB[2][LMAX + 2];
  float  redA[16];
  float  redB[16];
  float  sc[MAXB];
  int    labs[LMAX];
  int    amLast;
};

__device__ __forceinline__ float lse2_fast(float a, float b) {
  float mx = fmaxf(a, b);
  float mn = fminf(a, b);
  return mx + __logf(1.0f + __expf(mn - mx));
}

__global__ void __launch_bounds__(THREADS, 1)
chain_kernel(const float* __restrict__ x, const float* __restrict__ trans,
             const int* __restrict__ labels, const int* __restrict__ durations,
             int T, int L, int nwork, int grid, int B,
             float* __restrict__ out, int out_size)
{
  extern __shared__ char smraw[];
  SmemLayout& sm = *reinterpret_cast<SmemLayout*>(smraw);

  const int  tid  = threadIdx.x;
  const int  lane = tid & 31;
  const int  w    = tid >> 5;

  if (blockIdx.x < (unsigned)nwork) {
    const int b = blockIdx.x;           // one batch per CTA: fwd + bwd chains

    const int jp = w * 8 + (lane >> 2);
    const int h  = lane & 3;
    const int j0 = 2 * jp, j1 = j0 + 1;
    const int cbase = h * 64;

    const int D   = durations[b];
    const int m   = D >> 1;
    const int nsA = m;                  // fwd: t = 1..m
    const int nsB = D - 1 - m;          // bwd: t = D-1..m+1
    const int mx  = max(nsA, nsB);

    // ---- M slices in fp16 registers: fwd (E[c][j]) and bwd (E[j][c]), 64 c x 2 j each
    __half2 mFA[32], mFB[32], mRA[32], mRB[32];
    #pragma unroll
    for (int k = 0; k < 32; ++k) {
      int c0 = cbase + 2 * k, c1 = c0 + 1;
      mFA[k] = __floats2half2_rn(__expf(trans[c0 * C + j0]), __expf(trans[c1 * C + j0]));
      mFB[k] = __floats2half2_rn(__expf(trans[c0 * C + j1]), __expf(trans[c1 * C + j1]));
      mRA[k] = __floats2half2_rn(__expf(trans[j0 * C + c0]), __expf(trans[j0 * C + c1]));
      mRB[k] = __floats2half2_rn(__expf(trans[j1 * C + c0]), __expf(trans[j1 * C + c1]));
    }
    for (int l = tid; l < L; l += THREADS) sm.labs[l] = labels[b * L + l];

    const float* xb = x + (size_t)b * T * C;

    // ---- init both chains
    if (tid < C) {
      float wA = __expf(xb[tid]);                        // fwd: exp(x[0])
      float wB = __expf(xb[(size_t)(D - 1) * C + tid]);  // bwd: exp(x[D-1])
      #pragma unroll
      for (int cp = 0; cp < 4; ++cp) {
        sm.p16A[0][cp * P16PITCH + tid] = __float2half_rn(wA);
        sm.p16B[0][cp * P16PITCH + tid] = __float2half_rn(wB);
      }
      sm.xtA[0][tid] = xb[(size_t)1 * C + tid];
      sm.xtB[0][tid] = xb[(size_t)(D - 1) * C + tid];
      float rA = wA, rB = wB;
      #pragma unroll
      for (int o = 16; o; o >>= 1) {
        rA += __shfl_xor_sync(0xffffffffu, rA, o);
        rB += __shfl_xor_sync(0xffffffffu, rB, o);
      }
      if (lane == 0) { sm.redA[w] = rA; sm.redB[w] = rB; }
    } else if (lane == 0) {
      sm.redA[w] = 0.0f; sm.redB[w] = 0.0f;
    }
    if (tid < LMAX + 2) {
      sm.nbA[0][tid] = NEGV; sm.nbA[1][tid] = NEGV;
      sm.nbB[0][tid] = NEGV; sm.nbB[1][tid] = NEGV;
    }
    __syncthreads();
    if (tid == 0) {
      sm.nbA[0][1] = xb[sm.labs[0]];
      sm.nbB[0][L] = 0.0f;
    }

    // ---- two-step-ahead x pipelines per chain (float2 at j0)
    auto ldxA = [&](int k) -> float2 {
      int tp = min(1 + k, T - 1);
      return *reinterpret_cast<const float2*>(xb + (size_t)tp * C + j0);
    };
    auto ldxB = [&](int k) -> float2 {
      int tp = max(D - 1 - k, 0);
      return *reinterpret_cast<const float2*>(xb + (size_t)tp * C + j0);
    };
    float2 xqA0 = ldxA(0), xqA1 = ldxA(1);
    float2 xqB0 = ldxB(0), xqB1 = ldxB(1);

    float logSA = 0.0f, logSB = 0.0f;
    int   cur   = 0;
    float wnA0 = 0, wnA1 = 0, wnB0 = 0, wnB1 = 0;

    const bool numA = (h == 1) && (jp < L);   // fwd numerator lanes
    const bool numB = (h == 3) && (jp < L);   // bwd numerator lanes
    int labA0 = 0, labB0 = 0, labB1 = -1;
    if (numA) labA0 = sm.labs[jp];
    if (numB) {
      labB0 = sm.labs[jp];
      labB1 = (jp + 1 < L) ? sm.labs[jp + 1] : -1;
    }

    const int prdoff = 336 * h;
    const int pwroff = h * P16PITCH + j0;

    for (int k = 0; k < mx; ++k) {
      __syncthreads();
      const bool actA  = k < nsA;
      const bool actB  = k < nsB;
      const bool moreB = (k + 1) < nsB;
      const int  nxt   = cur ^ 1;

      // ---- heads: lagged normalizers (both latency-hidden under the GEMVs)
      float SA = sm.redA[lane & 15];
      float SB = sm.redB[lane & 15];
      #pragma unroll
      for (int o = 8; o; o >>= 1) {
        SA += __shfl_xor_sync(0xffffffffu, SA, o);
        SB += __shfl_xor_sync(0xffffffffu, SB, o);
      }
      float rsA = __fdividef(1.0f, SA);
      float rsB = __fdividef(1.0f, SB);

      float2 xqA2 = ldxA(k + 2);
      float2 xqB2 = ldxB(k + 2);

      // ---- GEMV A (fwd)
      const uint4* phA = reinterpret_cast<const uint4*>(sm.p16A[cur] + prdoff);
      __half2 z = __float2half2_rn(0.0f);
      __half2 aA0 = z, aA1 = z, aA2 = z, aA3 = z;
      __half2 bA0 = z, bA1 = z, bA2 = z, bA3 = z;
      #pragma unroll
      for (int q = 0; q < 8; ++q) {
        uint4 pm = phA[q];
        const __half2* p2 = reinterpret_cast<const __half2*>(&pm);
        aA0 = __hfma2(p2[0], mFA[4 * q + 0], aA0);
        aA1 = __hfma2(p2[1], mFA[4 * q + 1], aA1);
        aA2 = __hfma2(p2[2], mFA[4 * q + 2], aA2);
        aA3 = __hfma2(p2[3], mFA[4 * q + 3], aA3);
        bA0 = __hfma2(p2[0], mFB[4 * q + 0], bA0);
        bA1 = __hfma2(p2[1], mFB[4 * q + 1], bA1);
        bA2 = __hfma2(p2[2], mFB[4 * q + 2], bA2);
        bA3 = __hfma2(p2[3], mFB[4 * q + 3], bA3);
      }
      // ---- GEMV B (bwd) — independent stream, fills A's stalls
      const uint4* phB = reinterpret_cast<const uint4*>(sm.p16B[cur] + prdoff);
      __half2 aB0 = z, aB1 = z, aB2 = z, aB3 = z;
      __half2 bB0 = z, bB1 = z, bB2 = z, bB3 = z;
      #pragma unroll
      for (int q = 0; q < 8; ++q) {
        uint4 pm = phB[q];
        const __half2* p2 = reinterpret_cast<const __half2*>(&pm);
        aB0 = __hfma2(p2[0], mRA[4 * q + 0], aB0);
        aB1 = __hfma2(p2[1], mRA[4 * q + 1], aB1);
        aB2 = __hfma2(p2[2], mRA[4 * q + 2], aB2);
        aB3 = __hfma2(p2[3], mRA[4 * q + 3], aB3);
        bB0 = __hfma2(p2[0], mRB[4 * q + 0], bB0);
        bB1 = __hfma2(p2[1], mRB[4 * q + 1], bB1);
        bB2 = __hfma2(p2[2], mRB[4 * q + 2], bB2);
        bB3 = __hfma2(p2[3], mRB[4 * q + 3], bB3);
      }

      // ---- reduces (two independent chains)
      aA0 = __hadd2(aA0, aA1); aA2 = __hadd2(aA2, aA3); aA0 = __hadd2(aA0, aA2);
      bA0 = __hadd2(bA0, bA1); bA2 = __hadd2(bA2, bA3); bA0 = __hadd2(bA0, bA2);
      aB0 = __hadd2(aB0, aB1); aB2 = __hadd2(aB2, aB3); aB0 = __hadd2(aB0, aB2);
      bB0 = __hadd2(bB0, bB1); bB2 = __hadd2(bB2, bB3); bB0 = __hadd2(bB0, bB2);
      float2 fA0 = __half22float2(aA0), fA1 = __half22float2(bA0);
      float2 fB0 = __half22float2(aB0), fB1 = __half22float2(bB0);
      float yA0 = fA0.x + fA0.y, yA1 = fA1.x + fA1.y;
      float yB0 = fB0.x + fB0.y, yB1 = fB1.x + fB1.y;
      yA0 += __shfl_xor_sync(0xffffffffu, yA0, 1);
      yA0 += __shfl_xor_sync(0xffffffffu, yA0, 2);
      yA1 += __shfl_xor_sync(0xffffffffu, yA1, 1);
      yA1 += __shfl_xor_sync(0xffffffffu, yA1, 2);
      yB0 += __shfl_xor_sync(0xffffffffu, yB0, 1);
      yB0 += __shfl_xor_sync(0xffffffffu, yB0, 2);
      yB1 += __shfl_xor_sync(0xffffffffu, yB1, 1);
      yB1 += __shfl_xor_sync(0xffffffffu, yB1, 2);

      // ---- chain A tail (fwd)
      if (actA) {
        wnA0 = yA0 * __expf(xqA0.x) * rsA;
        wnA1 = yA1 * __expf(xqA0.y) * rsA;
        *reinterpret_cast<__half2*>(&sm.p16A[nxt][pwroff]) =
            __floats2half2_rn(wnA0, wnA1);
      }
      {
        float rv = (h == 0 && actA) ? (wnA0 + wnA1) : 0.0f;
        rv += __shfl_xor_sync(0xffffffffu, rv, 4);
        rv += __shfl_xor_sync(0xffffffffu, rv, 8);
        rv += __shfl_xor_sync(0xffffffffu, rv, 16);
        if (lane == 0 && actA) sm.redA[w] = rv;
      }
      // ---- chain B tail (bwd)
      if (actB) {
        wnB0 = yB0 * rsB;
        wnB1 = yB1 * rsB;
        if (moreB) { wnB0 *= __expf(xqB1.x); wnB1 *= __expf(xqB1.y); }
        *reinterpret_cast<__half2*>(&sm.p16B[nxt][pwroff]) =
            __floats2half2_rn(wnB0, wnB1);
      }
      {
        float rv = (h == 0 && actB) ? (wnB0 + wnB1) : 0.0f;
        rv += __shfl_xor_sync(0xffffffffu, rv, 4);
        rv += __shfl_xor_sync(0xffffffffu, rv, 8);
        rv += __shfl_xor_sync(0xffffffffu, rv, 16);
        if (lane == 0 && actB) sm.redB[w] = rv;
      }

      if (h == 2) {
        if (actA) *reinterpret_cast<float2*>(&sm.xtA[nxt][j0]) = xqA1;
        if (actB) *reinterpret_cast<float2*>(&sm.xtB[nxt][j0]) = xqB1;
      }

      if (numA && actA) {
        int l = jp;
        float e = sm.xtA[cur][labA0];
        sm.nbA[nxt][l + 1] = lse2_fast(sm.nbA[cur][l + 1], sm.nbA[cur][l]) + e;
      }
      if (numB && actB) {
        int l = jp;
        float v0 = sm.nbB[cur][l + 1] + sm.xtB[cur][labB0];
        float v1 = NEGV;
        if (labB1 >= 0) v1 = sm.nbB[cur][l + 2] + sm.xtB[cur][labB1];
        sm.nbB[nxt][l + 1] = lse2_fast(v0, v1);
      }

      if (tid == 0) {
        if (actA) logSA += __logf(SA);
        if (actB) logSB += __logf(SB);
      }

      xqA0 = xqA1; xqA1 = xqA2;
      xqB0 = xqB1; xqB1 = xqB2;
      cur ^= 1;
    }
    __syncthreads();

    float SfA = sm.redA[lane & 15];
    float SfB = sm.redB[lane & 15];
    #pragma unroll
    for (int o = 8; o; o >>= 1) {
      SfA += __shfl_xor_sync(0xffffffffu, SfA, o);
      SfB += __shfl_xor_sync(0xffffffffu, SfB, o);
    }

    if (h == 0) {
      g_f[b][j0] = wnA0 / SfA;  g_f[b][j1] = wnA1 / SfA;
      g_g[b][j0] = wnB0 / SfB;  g_g[b][j1] = wnB1 / SfB;
    }
    if (tid < L) {
      g_a [b][tid] = sm.nbA[nsA & 1][tid + 1];
      g_bt[b][tid] = sm.nbB[nsB & 1][tid + 1];
    }
    if (tid == 0) {
      g_lsf[b] = logSA + logf(SfA);
      g_lsg[b] = logSB + logf(SfB);
    }
    __syncthreads();
  }

  // ---- last-CTA-done combine ----
  if (tid == 0) {
    __threadfence();
    int ticket = atomicAdd(&g_bar, 1);
    sm.amLast = (ticket == grid - 1);
  }
  __syncthreads();
  if (!sm.amLast) return;
  __threadfence();

  for (int b2 = w; b2 < B; b2 += 16) {
    float dot = 0.0f;
    for (int c = lane; c < C; c += 32) dot += g_f[b2][c] * g_g[b2][c];
    #pragma unroll
    for (int o = 16; o; o >>= 1) dot += __shfl_xor_sync(0xffffffffu, dot, o);

    float mxv = -INFINITY;
    for (int l = lane; l < L; l += 32) mxv = fmaxf(mxv, g_a[b2][l] + g_bt[b2][l]);
    #pragma unroll
    for (int o = 16; o; o >>= 1) mxv = fmaxf(mxv, __shfl_xor_sync(0xffffffffu, mxv, o));

    float s = 0.0f;
    for (int l = lane; l < L; l += 32) s += expf(g_a[b2][l] + g_bt[b2][l] - mxv);
    #pragma unroll
    for (int o = 16; o; o >>= 1) s += __shfl_xor_sync(0xffffffffu, s, o);

    if (lane == 0) {
      float num = mxv + logf(s);
      float den = logf(dot) + g_lsf[b2] + g_lsg[b2];
      sm.sc[b2] = num - den;
    }
  }
  __syncthreads();
  if (tid == 0) {
    float tot = 0.0f;
    for (int i = 0; i < B; ++i) tot += sm.sc[i];
    long long fr = 0;
    for (int i = 0; i < B; ++i) fr += durations[i];
    out[0] = tot;
    if (out_size > 1) out[1] = (float)fr;
    if (out_size > 2) out[2] = (float)fr;
    g_bar = 0;
    __threadfence();
  }
}

extern "C" void kernel_launch(void* const* d_in, const int* in_sizes, int n_in,
                              void* d_out, int out_size)
{
  const float* x      = (const float*)d_in[0];
  const float* trans  = (const float*)d_in[1];
  const int*   labels = (const int*)d_in[2];
  const int*   dur    = (const int*)d_in[3];

  int B = in_sizes[3];
  int L = in_sizes[2] / B;
  int T = in_sizes[0] / (B * C);
  int nwork = B;                       // one CTA per batch (fwd+bwd fused)
  int grid  = nwork < GRID_PAD ? GRID_PAD : nwork;

  size_t smem = sizeof(SmemLayout);
  cudaFuncSetAttribute(chain_kernel, cudaFuncAttributeMaxDynamicSharedMemorySize, (int)smem);

  chain_kernel<<<grid, THREADS, smem>>>(x, trans, labels, dur, T, L,
                                        nwork, grid, B, (float*)d_out, out_size);
}

// round 17
// speedup vs baseline: 3.9837x; 3.9837x over previous
#include <cuda_runtime.h>
#include <cuda_fp16.h>
#include <math.h>

#define NEGV (-1e30f)

constexpr int C        = 256;
constexpr int LMAX     = 128;
constexpr int THREADS  = 512;   // 16 warps
constexpr int MAXB     = 64;
constexpr int P16PITCH = 272;   // halves per fp16 p copy (reads & writes bank-conflict-free)
constexpr int GRID_PAD = 148;

__device__ float g_f  [MAXB][C];
__device__ float g_g  [MAXB][C];
__device__ float g_a  [MAXB][LMAX];
__device__ float g_bt [MAXB][LMAX];
__device__ float g_lsf[MAXB];
__device__ float g_lsg[MAXB];
__device__ int   g_bar = 0;     // last-CTA ticket; reset by the combiner every call

struct SmemLayout {
  __half p16[2][4 * P16PITCH];    // fp16 p, 4 bank-shifted copies, double-buffered
  float  xt[2][C];                // x_t tiles for numerator gather
  float  nb[2][LMAX + 2];         // numerator DP (log domain)
  float  red[16];                 // per-warp w sums (1-lag normalizer)
  float  sc[MAXB];                // per-batch scores (combine phase)
  int    labs[LMAX];
  int    amLast;
};

__device__ __forceinline__ float lse2_fast(float a, float b) {
  float mx = fmaxf(a, b);
  float mn = fminf(a, b);
  return mx + __logf(1.0f + __expf(mn - mx));
}

__global__ void __launch_bounds__(THREADS, 1)
chain_kernel(const float* __restrict__ x, const float* __restrict__ trans,
             const int* __restrict__ labels, const int* __restrict__ durations,
             int T, int L, int nwork, int grid, int B,
             float* __restrict__ out, int out_size)
{
  extern __shared__ char smraw[];
  SmemLayout& sm = *reinterpret_cast<SmemLayout*>(smraw);

  const int  tid  = threadIdx.x;
  const int  lane = tid & 31;
  const int  w    = tid >> 5;

  if (blockIdx.x < (unsigned)nwork) {
    const int  b    = blockIdx.x >> 1;
    const bool bwd  = blockIdx.x & 1;

    const int jp = w * 8 + (lane >> 2);   // j-pair 0..127
    const int h  = lane & 3;              // c-quarter
    const int j0 = 2 * jp, j1 = j0 + 1;
    const int cbase = h * 64;

    const int D      = durations[b];
    const int m      = D >> 1;
    const int nsteps = bwd ? (D - 1 - m) : m;
    const int dt     = bwd ? -1 : 1;
    const int t0     = bwd ? (D - 1) : 1;     // t_k = t0 + dt*k

    // ---- ALL of M in fp16 registers: 64 c (c-paired half2) x 2 j
    __half2 mA[32], mB[32];
    #pragma unroll
    for (int k = 0; k < 32; ++k) {
      int c0 = cbase + 2 * k, c1 = c0 + 1;
      float a0, a1, b0, b1;
      if (!bwd) {
        a0 = __expf(trans[c0 * C + j0]); a1 = __expf(trans[c1 * C + j0]);
        b0 = __expf(trans[c0 * C + j1]); b1 = __expf(trans[c1 * C + j1]);
      } else {
        a0 = __expf(trans[j0 * C + c0]); a1 = __expf(trans[j0 * C + c1]);
        b0 = __expf(trans[j1 * C + c0]); b1 = __expf(trans[j1 * C + c1]);
      }
      mA[k] = __floats2half2_rn(a0, a1);
      mB[k] = __floats2half2_rn(b0, b1);
    }
    for (int l = tid; l < L; l += THREADS) sm.labs[l] = labels[b * L + l];

    const float* xb = x + (size_t)b * T * C;

    // ---- init p16 (4 copies), red, xt, nb
    if (tid < C) {
      int tp = bwd ? (D - 1) : 0;
      float w0 = __expf(xb[(size_t)tp * C + tid]);
      #pragma unroll
      for (int cp = 0; cp < 4; ++cp)
        sm.p16[0][cp * P16PITCH + tid] = __float2half_rn(w0);
      sm.xt[0][tid] = xb[(size_t)t0 * C + tid];
      float rv = w0;
      #pragma unroll
      for (int o = 16; o; o >>= 1) rv += __shfl_xor_sync(0xffffffffu, rv, o);
      if (lane == 0) sm.red[w] = rv;
    } else if (lane == 0) {
      sm.red[w] = 0.0f;
    }
    if (tid < LMAX + 2) { sm.nb[0][tid] = NEGV; sm.nb[1][tid] = NEGV; }
    __syncthreads();
    if (tid == 0) {
      if (!bwd) sm.nb[0][1] = xb[sm.labs[0]];
      else      sm.nb[0][L] = 0.0f;
    }

    // ---- two-step-ahead x + exp(x) pipelines (per-thread float2 at j0)
    auto ldx = [&](int k) -> float2 {
      int tp = t0 + dt * k;
      tp = max(0, min(tp, T - 1));
      return *reinterpret_cast<const float2*>(xb + (size_t)tp * C + j0);
    };
    float2 xq0 = ldx(0);
    float2 xq1 = ldx(1);
    float2 exq0 = make_float2(__expf(xq0.x), __expf(xq0.y));
    float2 exq1 = make_float2(__expf(xq1.x), __expf(xq1.y));

    float logS = 0.0f;
    int   cur  = 0;
    float wn0 = 0.0f, wn1 = 0.0f;

    const bool isnum = (h == 1);
    const int  lnum  = jp;
    int lab0 = 0, lab1 = -1;
    if (isnum && lnum < L) {
      lab0 = sm.labs[lnum];
      lab1 = (lnum + 1 < L) ? sm.labs[lnum + 1] : -1;
    }

    const int prdoff = 336 * h;            // copy h, c offset 64h (16B aligned)
    const int pwroff = h * P16PITCH + j0;

    for (int k = 0; k < nsteps; ++k) {
      __syncthreads();   // p16[cur], xt[cur], nb[cur], red visible
      const bool more = (k + 1) < nsteps;
      const int  nxt  = cur ^ 1;

      // ---- lagged normalizer (previous step's sum); latency-hidden under GEMV
      float S = sm.red[lane & 15];
      #pragma unroll
      for (int o = 8; o; o >>= 1) S += __shfl_xor_sync(0xffffffffu, S, o);
      float rs = __fdividef(1.0f, S);

      float2 xq2 = ldx(k + 2);   // consumed at step k+2

      // ---- GEMV quarter: 8 LDS.128 of p16 + 64 HFMA2, 4 accumulators per j
      const uint4* ph = reinterpret_cast<const uint4*>(sm.p16[cur] + prdoff);
      __half2 z = __float2half2_rn(0.0f);
      __half2 a0 = z, a1 = z, a2 = z, a3 = z;
      __half2 b0 = z, b1 = z, b2 = z, b3 = z;
      #pragma unroll
      for (int q = 0; q < 8; ++q) {
        uint4 pm = ph[q];
        const __half2* p2 = reinterpret_cast<const __half2*>(&pm);
        a0 = __hfma2(p2[0], mA[4 * q + 0], a0);
        a1 = __hfma2(p2[1], mA[4 * q + 1], a1);
        a2 = __hfma2(p2[2], mA[4 * q + 2], a2);
        a3 = __hfma2(p2[3], mA[4 * q + 3], a3);
        b0 = __hfma2(p2[0], mB[4 * q + 0], b0);
        b1 = __hfma2(p2[1], mB[4 * q + 1], b1);
        b2 = __hfma2(p2[2], mB[4 * q + 2], b2);
        b3 = __hfma2(p2[3], mB[4 * q + 3], b3);
      }
      a0 = __hadd2(a0, a1);  a2 = __hadd2(a2, a3);  a0 = __hadd2(a0, a2);
      b0 = __hadd2(b0, b1);  b2 = __hadd2(b2, b3);  b0 = __hadd2(b0, b2);
      float2 fa = __half22float2(a0);
      float2 fb = __half22float2(b0);
      float y0 = fa.x + fa.y;
      float y1 = fb.x + fb.y;
      y0 += __shfl_xor_sync(0xffffffffu, y0, 1);
      y0 += __shfl_xor_sync(0xffffffffu, y0, 2);
      y1 += __shfl_xor_sync(0xffffffffu, y1, 1);
      y1 += __shfl_xor_sync(0xffffffffu, y1, 2);

      // ---- wn: pure FMA tail (exp factors precomputed 2 steps ahead)
      if (!bwd) {
        wn0 = y0 * exq0.x * rs;
        wn1 = y1 * exq0.y * rs;
      } else {
        wn0 = y0 * rs;
        wn1 = y1 * rs;
        if (more) { wn0 *= exq1.x; wn1 *= exq1.y; }
      }
      *reinterpret_cast<__half2*>(&sm.p16[nxt][pwroff]) =
          __floats2half2_rn(wn0, wn1);

      { // per-step red (h==0 contributes) — R12 scheme, unchanged
        float rv = (h == 0) ? (wn0 + wn1) : 0.0f;
        rv += __shfl_xor_sync(0xffffffffu, rv, 4);
        rv += __shfl_xor_sync(0xffffffffu, rv, 8);
        rv += __shfl_xor_sync(0xffffffffu, rv, 16);
        if (lane == 0) sm.red[w] = rv;
      }

      if (h == 2 && more)
        *reinterpret_cast<float2*>(&sm.xt[nxt][j0]) = xq1;   // x[t_{k+1}]

      if (isnum && lnum < L) {
        int l = lnum;
        float nnew;
        if (!bwd) {
          float e = sm.xt[cur][lab0];
          nnew = lse2_fast(sm.nb[cur][l + 1], sm.nb[cur][l]) + e;
        } else {
          float v0 = sm.nb[cur][l + 1] + sm.xt[cur][lab0];
          float v1 = NEGV;
          if (lab1 >= 0) v1 = sm.nb[cur][l + 2] + sm.xt[cur][lab1];
          nnew = lse2_fast(v0, v1);
        }
        sm.nb[nxt][l + 1] = nnew;
      }

      if (tid == 0) logS += __logf(S);

      // ---- rotation: exp for step k+2 issues here, completes under the barrier
      float2 exq2 = make_float2(__expf(xq2.x), __expf(xq2.y));
      xq0 = xq1;   xq1 = xq2;
      exq0 = exq1; exq1 = exq2;
      cur ^= 1;
    }
    __syncthreads();

    float Sf = sm.red[lane & 15];
    #pragma unroll
    for (int o = 8; o; o >>= 1) Sf += __shfl_xor_sync(0xffffffffu, Sf, o);

    if (!bwd) {
      if (h == 0) {
        g_f[b][j0] = wn0 / Sf;
        g_f[b][j1] = wn1 / Sf;
      }
      if (tid < L)  g_a[b][tid] = sm.nb[cur][tid + 1];
      if (tid == 0) g_lsf[b] = logS + logf(Sf);
    } else {
      if (h == 0) {
        g_g[b][j0] = wn0 / Sf;
        g_g[b][j1] = wn1 / Sf;
      }
      if (tid < L)  g_bt[b][tid] = sm.nb[cur][tid + 1];
      if (tid == 0) g_lsg[b] = logS + logf(Sf);
    }
    __syncthreads();
  }

  // ---- last-CTA-done: the final arriver performs the combine ----
  if (tid == 0) {
    __threadfence();                       // release g_f/g_a/g_lsf...
    int ticket = atomicAdd(&g_bar, 1);
    sm.amLast = (ticket == grid - 1);
  }
  __syncthreads();
  if (!sm.amLast) return;
  __threadfence();                         // acquire others' writes

  // combine (512 threads, warp per batch)
  for (int b2 = w; b2 < B; b2 += 16) {
    float dot = 0.0f;
    for (int c = lane; c < C; c += 32) dot += g_f[b2][c] * g_g[b2][c];
    #pragma unroll
    for (int o = 16; o; o >>= 1) dot += __shfl_xor_sync(0xffffffffu, dot, o);

    float mx = -INFINITY;
    for (int l = lane; l < L; l += 32) mx = fmaxf(mx, g_a[b2][l] + g_bt[b2][l]);
    #pragma unroll
    for (int o = 16; o; o >>= 1) mx = fmaxf(mx, __shfl_xor_sync(0xffffffffu, mx, o));

    float s = 0.0f;
    for (int l = lane; l < L; l += 32) s += expf(g_a[b2][l] + g_bt[b2][l] - mx);
    #pragma unroll
    for (int o = 16; o; o >>= 1) s += __shfl_xor_sync(0xffffffffu, s, o);

    if (lane == 0) {
      float num = mx + logf(s);
      float den = logf(dot) + g_lsf[b2] + g_lsg[b2];
      sm.sc[b2] = num - den;
    }
  }
  __syncthreads();
  if (tid == 0) {
    float tot = 0.0f;
    for (int i = 0; i < B; ++i) tot += sm.sc[i];   // fixed order => deterministic
    long long fr = 0;
    for (int i = 0; i < B; ++i) fr += durations[i];
    out[0] = tot;
    if (out_size > 1) out[1] = (float)fr;
    if (out_size > 2) out[2] = (float)fr;
    g_bar = 0;                                     // reset for next (graph) call
    __threadfence();
  }
}

extern "C" void kernel_launch(void* const* d_in, const int* in_sizes, int n_in,
                              void* d_out, int out_size)
{
  const float* x      = (const float*)d_in[0];
  const float* trans  = (const float*)d_in[1];
  const int*   labels = (const int*)d_in[2];
  const int*   dur    = (const int*)d_in[3];

  int B = in_sizes[3];
  int L = in_sizes[2] / B;
  int T = in_sizes[0] / (B * C);
  int nwork = 2 * B;
  int grid  = nwork < GRID_PAD ? GRID_PAD : nwork;

  size_t smem = sizeof(SmemLayout);
  cudaFuncSetAttribute(chain_kernel, cudaFuncAttributeMaxDynamicSharedMemorySize, (int)smem);

  chain_kernel<<<grid, THREADS, smem>>>(x, trans, labels, dur, T, L,
                                        nwork, grid, B, (float*)d_out, out_size);
}